// round 16
// baseline (speedup 1.0000x reference)
#include <cuda_runtime.h>
#include <cuda_bf16.h>
#include <math.h>
#include <stdint.h>

#define BB 32
#define SS 8192
#define DD 256
#define HH 256
#define NCH 128            // m-chunks per batch (SS/MT)

// device-global scratch (allocation-free rule)
__device__ float g_inp[BB * HH];
__device__ __nv_bfloat16 g_Bh[HH * DD];      // W_ctx hi (bf16), [h][d]
__device__ __nv_bfloat16 g_Bl[HH * DD];      // W_ctx lo
__device__ float g_csum[BB * NCH * 2];       // per (batch, chunk, warp) expsum
__device__ unsigned long long g_cmax[BB * NCH * 2];  // packed (key<<32 | ~idx)

// ---------------------------------------------------------------------------
__device__ __forceinline__ uint32_t smem_u32(const void* p) {
    uint32_t a;
    asm("{ .reg .u64 t; cvta.to.shared.u64 t, %1; cvt.u32.u64 %0, t; }" : "=r"(a) : "l"(p));
    return a;
}
#define CP_ASYNC16(dst, src) \
    asm volatile("cp.async.cg.shared.global [%0], [%1], 16;" :: "r"(dst), "l"(src))
#define CP_COMMIT() asm volatile("cp.async.commit_group;" ::: "memory")
#define CP_WAIT0()  asm volatile("cp.async.wait_group 0;" ::: "memory")

#define LDSM4(r0, r1, r2, r3, a) \
    asm volatile("ldmatrix.sync.aligned.m8n8.x4.shared.b16 {%0,%1,%2,%3}, [%4];" \
        : "=r"(r0), "=r"(r1), "=r"(r2), "=r"(r3) : "r"(a))

#define MMA_BF16(c, A, b0, b1) \
    asm volatile("mma.sync.aligned.m16n8k16.row.col.f32.bf16.bf16.f32 " \
        "{%0,%1,%2,%3},{%4,%5,%6,%7},{%8,%9},{%0,%1,%2,%3};" \
        : "+f"((c)[0]), "+f"((c)[1]), "+f"((c)[2]), "+f"((c)[3]) \
        : "r"((A)[0]), "r"((A)[1]), "r"((A)[2]), "r"((A)[3]), "r"(b0), "r"(b1))

// order-preserving float -> uint32 key
__device__ __forceinline__ uint32_t fkey(float v) {
    uint32_t u = __float_as_uint(v);
    return (u & 0x80000000u) ? ~u : (u | 0x80000000u);
}
__device__ __forceinline__ float fkey_inv(uint32_t k) {
    uint32_t u = (k & 0x80000000u) ? (k & 0x7fffffffu) : ~k;
    return __uint_as_float(u);
}

// ---------------------------------------------------------------------------
// Kernel 1 (prep): block b computes inp[b,:] and splits its 1/32 W slice.
// ---------------------------------------------------------------------------
__global__ __launch_bounds__(256) void k_prep(const float* __restrict__ x,
                                              const float* __restrict__ W_in,
                                              const float* __restrict__ b_in,
                                              const float* __restrict__ W_ctx) {
    int b = blockIdx.x, h = threadIdx.x;
    __shared__ float xs[HH];
    xs[h] = x[b * HH + h];
    __syncthreads();
    float acc = b_in[h];
    const float* w = W_in + h * HH;
#pragma unroll 8
    for (int d0 = 0; d0 < HH; d0 += 4) {
        float4 w4 = *(const float4*)(w + d0);
        acc += xs[d0] * w4.x + xs[d0+1] * w4.y + xs[d0+2] * w4.z + xs[d0+3] * w4.w;
    }
    g_inp[b * HH + h] = acc;

#pragma unroll
    for (int r = 0; r < 8; r++) {
        int i = b * 2048 + h + 256 * r;
        float v = W_ctx[i];
        __nv_bfloat16 hi = __float2bfloat16_rn(v);
        g_Bh[i] = hi;
        g_Bl[i] = __float2bfloat16_rn(v - __bfloat162float(hi));
    }
}

// ---------------------------------------------------------------------------
// Kernel 2: split-bf16 HMMA GEMM + FULLY fused epilogue (R7 GEMM verbatim):
// per-row tanh-dot, mask echo, masked exp-sum + packed argmax, one
// (u64,float) pair per warp-of-rows written to fixed slots (deterministic).
// CTA: M=64 rows, N=256, K=256 in 8 tiles of 32, double-buffered.
// acc = Ah*Bh + Ah*Bl + Al*Bh   (lo*lo dropped ~2^-18)
// ---------------------------------------------------------------------------
#define MT 64
#define KT 32
#define PITCH 80
#define OFF_A   0
#define OFF_B   20480
#define OFF_IB  102400
#define OFF_V   103424
#define OFF_P   104448
#define SMEM_TOTAL 105472

__global__ __launch_bounds__(256, 2) void k_main(const float* __restrict__ context,
                                                 const float* __restrict__ b_ctx,
                                                 const float* __restrict__ V,
                                                 const int* __restrict__ mask,
                                                 float* __restrict__ out) {
    extern __shared__ char smem[];
    uint32_t sb = smem_u32(smem);
    int tid = threadIdx.x;
    int wid = tid >> 5, lid = tid & 31;
    int wm = wid & 1, wn = wid >> 1;
    int b = blockIdx.y;
    int m0 = blockIdx.x * MT;

    float* ibs = (float*)(smem + OFF_IB);
    float* vvs = (float*)(smem + OFF_V);
    ibs[tid] = g_inp[b * HH + tid] + b_ctx[tid];
    vvs[tid] = V[tid];

    const float* ctx = context + ((long)b * SS + m0) * DD;

    int arow = tid >> 2, aseg = tid & 3;
    const float* aptr = ctx + arow * DD + aseg * 8;
    {
        int k0 = 0;
#pragma unroll
        for (int r = 0; r < 8; r++) {
            int idx = tid + 256 * r;
            int mat = idx >> 10, rem = idx & 1023;
            int row = rem >> 2, c = rem & 3;
            const __nv_bfloat16* src = (mat ? g_Bl : g_Bh) + row * DD + k0 + c * 8;
            uint32_t dst = sb + OFF_B + mat * 20480 + row * PITCH + c * 16;
            CP_ASYNC16(dst, src);
        }
        CP_COMMIT();
    }
    float4 a0 = *(const float4*)(aptr);
    float4 a1 = *(const float4*)(aptr + 4);

    float c[2][8][4];
#pragma unroll
    for (int mi = 0; mi < 2; mi++)
#pragma unroll
        for (int j = 0; j < 8; j++)
#pragma unroll
            for (int e = 0; e < 4; e++) c[mi][j][e] = 0.f;

    for (int kt = 0; kt < DD / KT; kt++) {
        int s = kt & 1;
        {
            float f[8] = {a0.x, a0.y, a0.z, a0.w, a1.x, a1.y, a1.z, a1.w};
            uint32_t hi[4], lo[4];
#pragma unroll
            for (int e = 0; e < 4; e++) {
                __nv_bfloat16 h0 = __float2bfloat16_rn(f[2*e]);
                __nv_bfloat16 h1 = __float2bfloat16_rn(f[2*e+1]);
                __nv_bfloat16 l0 = __float2bfloat16_rn(f[2*e]   - __bfloat162float(h0));
                __nv_bfloat16 l1 = __float2bfloat16_rn(f[2*e+1] - __bfloat162float(h1));
                hi[e] = (uint32_t)__bfloat16_as_ushort(h0) | ((uint32_t)__bfloat16_as_ushort(h1) << 16);
                lo[e] = (uint32_t)__bfloat16_as_ushort(l0) | ((uint32_t)__bfloat16_as_ushort(l1) << 16);
            }
            char* base = smem + OFF_A + s * 10240 + arow * PITCH + aseg * 16;
            *(uint4*)(base)         = make_uint4(hi[0], hi[1], hi[2], hi[3]);
            *(uint4*)(base + 5120)  = make_uint4(lo[0], lo[1], lo[2], lo[3]);
        }
        CP_WAIT0();
        __syncthreads();

        if (kt < DD / KT - 1) {
            int k0 = (kt + 1) * KT;
#pragma unroll
            for (int r = 0; r < 8; r++) {
                int idx = tid + 256 * r;
                int mat = idx >> 10, rem = idx & 1023;
                int row = rem >> 2, cc = rem & 3;
                const __nv_bfloat16* src = (mat ? g_Bl : g_Bh) + row * DD + k0 + cc * 8;
                uint32_t dst = sb + OFF_B + (s ^ 1) * 2 * 20480 + mat * 20480 + row * PITCH + cc * 16;
                CP_ASYNC16(dst, src);
            }
            CP_COMMIT();
            const float* ap = ctx + arow * DD + k0 + aseg * 8;
            a0 = *(const float4*)(ap);
            a1 = *(const float4*)(ap + 4);
        }

        uint32_t abase = sb + OFF_A + s * 10240;
        uint32_t bbase = sb + OFF_B + s * 2 * 20480;
#pragma unroll
        for (int ks = 0; ks < 2; ks++) {
            uint32_t aH[2][4], aL[2][4], bH[4][4], bL[4][4];
            int arow_f = wm * 32 + (lid & 15);
            int acol_b = ks * 32 + (lid >> 4) * 16;
#pragma unroll
            for (int mi = 0; mi < 2; mi++) {
                uint32_t ad = abase + (arow_f + mi * 16) * PITCH + acol_b;
                LDSM4(aH[mi][0], aH[mi][1], aH[mi][2], aH[mi][3], ad);
                LDSM4(aL[mi][0], aL[mi][1], aL[mi][2], aL[mi][3], ad + 5120);
            }
            int brow_f = wn * 64 + (lid & 7) + ((lid >> 4) * 8);
            int bcol_b = ks * 32 + ((lid >> 3) & 1) * 16;
#pragma unroll
            for (int jp = 0; jp < 4; jp++) {
                uint32_t bd = bbase + (brow_f + jp * 16) * PITCH + bcol_b;
                LDSM4(bH[jp][0], bH[jp][1], bH[jp][2], bH[jp][3], bd);
                LDSM4(bL[jp][0], bL[jp][1], bL[jp][2], bL[jp][3], bd + 20480);
            }
#pragma unroll
            for (int mi = 0; mi < 2; mi++)
#pragma unroll
                for (int j = 0; j < 8; j++) {
                    uint32_t h0 = bH[j >> 1][(j & 1) * 2], h1 = bH[j >> 1][(j & 1) * 2 + 1];
                    uint32_t l0 = bL[j >> 1][(j & 1) * 2], l1 = bL[j >> 1][(j & 1) * 2 + 1];
                    MMA_BF16(c[mi][j], aH[mi], h0, h1);
                    MMA_BF16(c[mi][j], aH[mi], l0, l1);
                    MMA_BF16(c[mi][j], aL[mi], h0, h1);
                }
        }
    }

    // ---- epilogue: tanh-dot, then fused mask echo + softmax stats ----
    {
        int q = lid & 3, g = lid >> 2;
        float ps[2][2] = {{0.f, 0.f}, {0.f, 0.f}};
#pragma unroll
        for (int mi = 0; mi < 2; mi++)
#pragma unroll
            for (int j = 0; j < 8; j++) {
                int h0 = wn * 64 + j * 8 + q * 2;
                ps[mi][0] += vvs[h0]   * tanhf(c[mi][j][0] + ibs[h0]);
                ps[mi][0] += vvs[h0+1] * tanhf(c[mi][j][1] + ibs[h0+1]);
                ps[mi][1] += vvs[h0]   * tanhf(c[mi][j][2] + ibs[h0]);
                ps[mi][1] += vvs[h0+1] * tanhf(c[mi][j][3] + ibs[h0+1]);
            }
#pragma unroll
        for (int off = 1; off <= 2; off <<= 1) {
#pragma unroll
            for (int mi = 0; mi < 2; mi++) {
                ps[mi][0] += __shfl_xor_sync(0xffffffffu, ps[mi][0], off);
                ps[mi][1] += __shfl_xor_sync(0xffffffffu, ps[mi][1], off);
            }
        }
        float* part = (float*)(smem + OFF_P);
        __syncthreads();
        if (q == 0) {
#pragma unroll
            for (int mi = 0; mi < 2; mi++) {
                part[(wm * 32 + mi * 16 + g) * 4 + wn]     = ps[mi][0];
                part[(wm * 32 + mi * 16 + g + 8) * 4 + wn] = ps[mi][1];
            }
        }
        __syncthreads();
        if (tid < MT) {        // warps 0 and 1, full
            float ssum = part[tid * 4] + part[tid * 4 + 1] + part[tid * 4 + 2] + part[tid * 4 + 3];
            float att = 10.f * tanhf(ssum);
            int gs = m0 + tid;
            int m = mask[b * SS + gs];
            out[2 * BB + b * SS + gs] = m ? 1.f : 0.f;
            float e = 0.f;
            unsigned long long packed = 0ull;
            if (m) {
                e = expf(att);     // att in [-10,10]: safe
                packed = ((unsigned long long)fkey(att) << 32) | (uint32_t)(~gs);
            }
#pragma unroll
            for (int off = 16; off; off >>= 1) {
                e += __shfl_xor_sync(0xffffffffu, e, off);
                unsigned long long o = __shfl_xor_sync(0xffffffffu, packed, off);
                if (o > packed) packed = o;
            }
            if (lid == 0) {
                int slot = (b * NCH + blockIdx.x) * 2 + wid;
                g_csum[slot] = e;
                g_cmax[slot] = packed;
            }
        }
    }
}

// ---------------------------------------------------------------------------
// Kernel 3: finisher — 1 CTA, 1024 threads = 32 batches x 32 lanes.
// Each lane reduces 8 fixed slots, then shfl within 32-lane segment.
// Fully deterministic (fixed reduction order, exact max).
// ---------------------------------------------------------------------------
__global__ __launch_bounds__(1024) void k_fin(float* __restrict__ out) {
    int t = threadIdx.x;
    int b = t >> 5, ln = t & 31;
    float se = 0.f;
    unsigned long long best = 0ull;
#pragma unroll
    for (int k = 0; k < 8; k++) {
        int slot = b * (NCH * 2) + ln * 8 + k;
        se += g_csum[slot];
        unsigned long long v = g_cmax[slot];
        if (v > best) best = v;
    }
#pragma unroll
    for (int off = 16; off; off >>= 1) {
        se += __shfl_xor_sync(0xffffffffu, se, off);
        unsigned long long o = __shfl_xor_sync(0xffffffffu, best, off);
        if (o > best) best = o;
    }
    if (ln == 0) {
        if (best == 0ull) {
            out[b] = 0.f;
            out[BB + b] = 0.f / se;     // se==0 -> nan, matches all-masked ref
        } else {
            uint32_t key = (uint32_t)(best >> 32);
            int idx = (int)(~(uint32_t)best);
            out[b]      = (float)idx;
            out[BB + b] = expf(fkey_inv(key)) / se;
        }
    }
}

// ---------------------------------------------------------------------------
extern "C" void kernel_launch(void* const* d_in, const int* in_sizes, int n_in,
                              void* d_out, int out_size) {
    const float* x      = (const float*)d_in[0];
    const float* contex = (const float*)d_in[1];
    const int*   mask   = (const int*)  d_in[2];
    const float* W_in   = (const float*)d_in[3];
    const float* b_in   = (const float*)d_in[4];
    const float* W_ctx  = (const float*)d_in[5];
    const float* b_ctx  = (const float*)d_in[6];
    const float* V      = (const float*)d_in[7];
    float* out = (float*)d_out;

    cudaFuncSetAttribute(k_main, cudaFuncAttributeMaxDynamicSharedMemorySize, SMEM_TOTAL);

    k_prep<<<BB, 256>>>(x, W_in, b_in, W_ctx);
    k_main<<<dim3(SS / MT, BB), 256, SMEM_TOTAL>>>(contex, b_ctx, V, mask, out);
    k_fin<<<1, 1024>>>(out);
}

// round 17
// speedup vs baseline: 1.0001x; 1.0001x over previous
#include <cuda_runtime.h>
#include <cuda_bf16.h>
#include <math.h>
#include <stdint.h>

#define BB 32
#define SS 8192
#define DD 256
#define HH 256
#define NCH 128            // m-chunks per batch (SS/MT)

// device-global scratch (allocation-free rule)
__device__ float g_inp[BB * HH];
__device__ __nv_bfloat16 g_Bh[HH * DD];      // W_ctx hi (bf16), [h][d]
__device__ __nv_bfloat16 g_Bl[HH * DD];      // W_ctx lo
__device__ float g_csum[BB * NCH * 2];       // per (batch, chunk, warp) expsum
__device__ unsigned long long g_cmax[BB * NCH * 2];  // packed (key<<32 | ~idx)

// ---------------------------------------------------------------------------
__device__ __forceinline__ uint32_t smem_u32(const void* p) {
    uint32_t a;
    asm("{ .reg .u64 t; cvta.to.shared.u64 t, %1; cvt.u32.u64 %0, t; }" : "=r"(a) : "l"(p));
    return a;
}
#define CP_ASYNC16(dst, src) \
    asm volatile("cp.async.cg.shared.global [%0], [%1], 16;" :: "r"(dst), "l"(src))
#define CP_COMMIT() asm volatile("cp.async.commit_group;" ::: "memory")
#define CP_WAIT0()  asm volatile("cp.async.wait_group 0;" ::: "memory")

#define LDSM4(r0, r1, r2, r3, a) \
    asm volatile("ldmatrix.sync.aligned.m8n8.x4.shared.b16 {%0,%1,%2,%3}, [%4];" \
        : "=r"(r0), "=r"(r1), "=r"(r2), "=r"(r3) : "r"(a))

#define MMA_BF16(c, A, b0, b1) \
    asm volatile("mma.sync.aligned.m16n8k16.row.col.f32.bf16.bf16.f32 " \
        "{%0,%1,%2,%3},{%4,%5,%6,%7},{%8,%9},{%0,%1,%2,%3};" \
        : "+f"((c)[0]), "+f"((c)[1]), "+f"((c)[2]), "+f"((c)[3]) \
        : "r"((A)[0]), "r"((A)[1]), "r"((A)[2]), "r"((A)[3]), "r"(b0), "r"(b1))

// order-preserving float -> uint32 key
__device__ __forceinline__ uint32_t fkey(float v) {
    uint32_t u = __float_as_uint(v);
    return (u & 0x80000000u) ? ~u : (u | 0x80000000u);
}
__device__ __forceinline__ float fkey_inv(uint32_t k) {
    uint32_t u = (k & 0x80000000u) ? (k & 0x7fffffffu) : ~k;
    return __uint_as_float(u);
}

// ---------------------------------------------------------------------------
// Kernel 1 (prep): block b computes inp[b,:] (warp-cooperative, coalesced)
// and splits its 1/32 W slice to bf16 hi/lo.
// ---------------------------------------------------------------------------
__global__ __launch_bounds__(256) void k_prep(const float* __restrict__ x,
                                              const float* __restrict__ W_in,
                                              const float* __restrict__ b_in,
                                              const float* __restrict__ W_ctx) {
    int b = blockIdx.x;
    int tid = threadIdx.x;
    int wid = tid >> 5, lid = tid & 31;
    __shared__ float xs[HH];
    xs[tid] = x[b * HH + tid];
    __syncthreads();

    // warp wid computes h = wid*32 .. wid*32+31; coalesced row reads
    float x0 = xs[lid * 8],     x1 = xs[lid * 8 + 1],
          x2 = xs[lid * 8 + 2], x3 = xs[lid * 8 + 3],
          x4 = xs[lid * 8 + 4], x5 = xs[lid * 8 + 5],
          x6 = xs[lid * 8 + 6], x7 = xs[lid * 8 + 7];
#pragma unroll 4
    for (int hh = 0; hh < 32; hh++) {
        int h = wid * 32 + hh;
        const float4* w = (const float4*)(W_in + h * HH);
        float4 wa = w[lid * 2], wb = w[lid * 2 + 1];
        float s = wa.x * x0 + wa.y * x1 + wa.z * x2 + wa.w * x3
                + wb.x * x4 + wb.y * x5 + wb.z * x6 + wb.w * x7;
#pragma unroll
        for (int off = 16; off; off >>= 1)
            s += __shfl_xor_sync(0xffffffffu, s, off);
        if (lid == 0) g_inp[b * HH + h] = s + b_in[h];
    }

    // W split: coalesced (consecutive threads -> consecutive i)
#pragma unroll
    for (int r = 0; r < 8; r++) {
        int i = b * 2048 + tid + 256 * r;
        float v = W_ctx[i];
        __nv_bfloat16 hi = __float2bfloat16_rn(v);
        g_Bh[i] = hi;
        g_Bl[i] = __float2bfloat16_rn(v - __bfloat162float(hi));
    }
}

// ---------------------------------------------------------------------------
// Kernel 2: split-bf16 HMMA GEMM + fully fused epilogue (R16 verbatim).
// CTA: M=64 rows, N=256, K=256 in 8 tiles of 32, double-buffered.
// acc = Ah*Bh + Ah*Bl + Al*Bh   (lo*lo dropped ~2^-18)
// ---------------------------------------------------------------------------
#define MT 64
#define KT 32
#define PITCH 80
#define OFF_A   0
#define OFF_B   20480
#define OFF_IB  102400
#define OFF_V   103424
#define OFF_P   104448
#define SMEM_TOTAL 105472

__global__ __launch_bounds__(256, 2) void k_main(const float* __restrict__ context,
                                                 const float* __restrict__ b_ctx,
                                                 const float* __restrict__ V,
                                                 const int* __restrict__ mask,
                                                 float* __restrict__ out) {
    extern __shared__ char smem[];
    uint32_t sb = smem_u32(smem);
    int tid = threadIdx.x;
    int wid = tid >> 5, lid = tid & 31;
    int wm = wid & 1, wn = wid >> 1;
    int b = blockIdx.y;
    int m0 = blockIdx.x * MT;

    float* ibs = (float*)(smem + OFF_IB);
    float* vvs = (float*)(smem + OFF_V);
    ibs[tid] = g_inp[b * HH + tid] + b_ctx[tid];
    vvs[tid] = V[tid];

    const float* ctx = context + ((long)b * SS + m0) * DD;

    int arow = tid >> 2, aseg = tid & 3;
    const float* aptr = ctx + arow * DD + aseg * 8;
    {
        int k0 = 0;
#pragma unroll
        for (int r = 0; r < 8; r++) {
            int idx = tid + 256 * r;
            int mat = idx >> 10, rem = idx & 1023;
            int row = rem >> 2, c = rem & 3;
            const __nv_bfloat16* src = (mat ? g_Bl : g_Bh) + row * DD + k0 + c * 8;
            uint32_t dst = sb + OFF_B + mat * 20480 + row * PITCH + c * 16;
            CP_ASYNC16(dst, src);
        }
        CP_COMMIT();
    }
    float4 a0 = *(const float4*)(aptr);
    float4 a1 = *(const float4*)(aptr + 4);

    float c[2][8][4];
#pragma unroll
    for (int mi = 0; mi < 2; mi++)
#pragma unroll
        for (int j = 0; j < 8; j++)
#pragma unroll
            for (int e = 0; e < 4; e++) c[mi][j][e] = 0.f;

    for (int kt = 0; kt < DD / KT; kt++) {
        int s = kt & 1;
        {
            float f[8] = {a0.x, a0.y, a0.z, a0.w, a1.x, a1.y, a1.z, a1.w};
            uint32_t hi[4], lo[4];
#pragma unroll
            for (int e = 0; e < 4; e++) {
                __nv_bfloat16 h0 = __float2bfloat16_rn(f[2*e]);
                __nv_bfloat16 h1 = __float2bfloat16_rn(f[2*e+1]);
                __nv_bfloat16 l0 = __float2bfloat16_rn(f[2*e]   - __bfloat162float(h0));
                __nv_bfloat16 l1 = __float2bfloat16_rn(f[2*e+1] - __bfloat162float(h1));
                hi[e] = (uint32_t)__bfloat16_as_ushort(h0) | ((uint32_t)__bfloat16_as_ushort(h1) << 16);
                lo[e] = (uint32_t)__bfloat16_as_ushort(l0) | ((uint32_t)__bfloat16_as_ushort(l1) << 16);
            }
            char* base = smem + OFF_A + s * 10240 + arow * PITCH + aseg * 16;
            *(uint4*)(base)         = make_uint4(hi[0], hi[1], hi[2], hi[3]);
            *(uint4*)(base + 5120)  = make_uint4(lo[0], lo[1], lo[2], lo[3]);
        }
        CP_WAIT0();
        __syncthreads();

        if (kt < DD / KT - 1) {
            int k0 = (kt + 1) * KT;
#pragma unroll
            for (int r = 0; r < 8; r++) {
                int idx = tid + 256 * r;
                int mat = idx >> 10, rem = idx & 1023;
                int row = rem >> 2, cc = rem & 3;
                const __nv_bfloat16* src = (mat ? g_Bl : g_Bh) + row * DD + k0 + cc * 8;
                uint32_t dst = sb + OFF_B + (s ^ 1) * 2 * 20480 + mat * 20480 + row * PITCH + cc * 16;
                CP_ASYNC16(dst, src);
            }
            CP_COMMIT();
            const float* ap = ctx + arow * DD + k0 + aseg * 8;
            a0 = *(const float4*)(ap);
            a1 = *(const float4*)(ap + 4);
        }

        uint32_t abase = sb + OFF_A + s * 10240;
        uint32_t bbase = sb + OFF_B + s * 2 * 20480;
#pragma unroll
        for (int ks = 0; ks < 2; ks++) {
            uint32_t aH[2][4], aL[2][4], bH[4][4], bL[4][4];
            int arow_f = wm * 32 + (lid & 15);
            int acol_b = ks * 32 + (lid >> 4) * 16;
#pragma unroll
            for (int mi = 0; mi < 2; mi++) {
                uint32_t ad = abase + (arow_f + mi * 16) * PITCH + acol_b;
                LDSM4(aH[mi][0], aH[mi][1], aH[mi][2], aH[mi][3], ad);
                LDSM4(aL[mi][0], aL[mi][1], aL[mi][2], aL[mi][3], ad + 5120);
            }
            int brow_f = wn * 64 + (lid & 7) + ((lid >> 4) * 8);
            int bcol_b = ks * 32 + ((lid >> 3) & 1) * 16;
#pragma unroll
            for (int jp = 0; jp < 4; jp++) {
                uint32_t bd = bbase + (brow_f + jp * 16) * PITCH + bcol_b;
                LDSM4(bH[jp][0], bH[jp][1], bH[jp][2], bH[jp][3], bd);
                LDSM4(bL[jp][0], bL[jp][1], bL[jp][2], bL[jp][3], bd + 20480);
            }
#pragma unroll
            for (int mi = 0; mi < 2; mi++)
#pragma unroll
                for (int j = 0; j < 8; j++) {
                    uint32_t h0 = bH[j >> 1][(j & 1) * 2], h1 = bH[j >> 1][(j & 1) * 2 + 1];
                    uint32_t l0 = bL[j >> 1][(j & 1) * 2], l1 = bL[j >> 1][(j & 1) * 2 + 1];
                    MMA_BF16(c[mi][j], aH[mi], h0, h1);
                    MMA_BF16(c[mi][j], aH[mi], l0, l1);
                    MMA_BF16(c[mi][j], aL[mi], h0, h1);
                }
        }
    }

    // ---- epilogue: tanh-dot, mask echo, masked exp-sum + packed argmax ----
    {
        int q = lid & 3, g = lid >> 2;
        float ps[2][2] = {{0.f, 0.f}, {0.f, 0.f}};
#pragma unroll
        for (int mi = 0; mi < 2; mi++)
#pragma unroll
            for (int j = 0; j < 8; j++) {
                int h0 = wn * 64 + j * 8 + q * 2;
                ps[mi][0] += vvs[h0]   * tanhf(c[mi][j][0] + ibs[h0]);
                ps[mi][0] += vvs[h0+1] * tanhf(c[mi][j][1] + ibs[h0+1]);
                ps[mi][1] += vvs[h0]   * tanhf(c[mi][j][2] + ibs[h0]);
                ps[mi][1] += vvs[h0+1] * tanhf(c[mi][j][3] + ibs[h0+1]);
            }
#pragma unroll
        for (int off = 1; off <= 2; off <<= 1) {
#pragma unroll
            for (int mi = 0; mi < 2; mi++) {
                ps[mi][0] += __shfl_xor_sync(0xffffffffu, ps[mi][0], off);
                ps[mi][1] += __shfl_xor_sync(0xffffffffu, ps[mi][1], off);
            }
        }
        float* part = (float*)(smem + OFF_P);
        __syncthreads();
        if (q == 0) {
#pragma unroll
            for (int mi = 0; mi < 2; mi++) {
                part[(wm * 32 + mi * 16 + g) * 4 + wn]     = ps[mi][0];
                part[(wm * 32 + mi * 16 + g + 8) * 4 + wn] = ps[mi][1];
            }
        }
        __syncthreads();
        if (tid < MT) {        // warps 0 and 1, full
            float ssum = part[tid * 4] + part[tid * 4 + 1] + part[tid * 4 + 2] + part[tid * 4 + 3];
            float att = 10.f * tanhf(ssum);
            int gs = m0 + tid;
            int m = mask[b * SS + gs];
            out[2 * BB + b * SS + gs] = m ? 1.f : 0.f;
            float e = 0.f;
            unsigned long long packed = 0ull;
            if (m) {
                e = expf(att);     // att in [-10,10]: safe
                packed = ((unsigned long long)fkey(att) << 32) | (uint32_t)(~gs);
            }
#pragma unroll
            for (int off = 16; off; off >>= 1) {
                e += __shfl_xor_sync(0xffffffffu, e, off);
                unsigned long long o = __shfl_xor_sync(0xffffffffu, packed, off);
                if (o > packed) packed = o;
            }
            if (lid == 0) {
                int slot = (b * NCH + blockIdx.x) * 2 + wid;
                g_csum[slot] = e;
                g_cmax[slot] = packed;
            }
        }
    }
}

// ---------------------------------------------------------------------------
// Kernel 3: finisher — 1 CTA, 1024 threads = 32 batches x 32 lanes.
// ---------------------------------------------------------------------------
__global__ __launch_bounds__(1024) void k_fin(float* __restrict__ out) {
    int t = threadIdx.x;
    int b = t >> 5, ln = t & 31;
    float se = 0.f;
    unsigned long long best = 0ull;
#pragma unroll
    for (int k = 0; k < 8; k++) {
        int slot = b * (NCH * 2) + ln * 8 + k;
        se += g_csum[slot];
        unsigned long long v = g_cmax[slot];
        if (v > best) best = v;
    }
#pragma unroll
    for (int off = 16; off; off >>= 1) {
        se += __shfl_xor_sync(0xffffffffu, se, off);
        unsigned long long o = __shfl_xor_sync(0xffffffffu, best, off);
        if (o > best) best = o;
    }
    if (ln == 0) {
        if (best == 0ull) {
            out[b] = 0.f;
            out[BB + b] = 0.f / se;     // se==0 -> nan, matches all-masked ref
        } else {
            uint32_t key = (uint32_t)(best >> 32);
            int idx = (int)(~(uint32_t)best);
            out[b]      = (float)idx;
            out[BB + b] = expf(fkey_inv(key)) / se;
        }
    }
}

// ---------------------------------------------------------------------------
extern "C" void kernel_launch(void* const* d_in, const int* in_sizes, int n_in,
                              void* d_out, int out_size) {
    const float* x      = (const float*)d_in[0];
    const float* contex = (const float*)d_in[1];
    const int*   mask   = (const int*)  d_in[2];
    const float* W_in   = (const float*)d_in[3];
    const float* b_in   = (const float*)d_in[4];
    const float* W_ctx  = (const float*)d_in[5];
    const float* b_ctx  = (const float*)d_in[6];
    const float* V      = (const float*)d_in[7];
    float* out = (float*)d_out;

    cudaFuncSetAttribute(k_main, cudaFuncAttributeMaxDynamicSharedMemorySize, SMEM_TOTAL);

    k_prep<<<BB, 256>>>(x, W_in, b_in, W_ctx);
    k_main<<<dim3(SS / MT, BB), 256, SMEM_TOTAL>>>(contex, b_ctx, V, mask, out);
    k_fin<<<1, 1024>>>(out);
}